// round 13
// baseline (speedup 1.0000x reference)
#include <cuda_runtime.h>
#include <cstdint>

#define NN 100000
#define EE 3200000
#define DD 64
#define ND4 (NN * DD / 4)        // 1,600,000 float4
#define BSH 5                    // 32 nodes per bucket
#define BSZ 32
#define NBUK (NN / BSZ)          // 3125 exactly
#define SCB 256
#define NSB ((NBUK + SCB - 1) / SCB)   // 13

// Scratch (static __device__ arrays; no allocation allowed)
__device__ int   g_deg[NN];
__device__ float g_dinv[NN];
__device__ int   g_bcnt[NBUK];
__device__ int   g_bfill[NBUK];
__device__ int   g_bptr[NBUK + 1];
__device__ int   g_sbs[NSB];
__device__ __align__(16) int4  g_eb[EE];     // bucketed: {src, col, bitcast(norm), 0}
__device__ __align__(16) float g_xa[NN * DD];
__device__ __align__(16) float g_xb[NN * DD];

// ---------------- preprocessing ----------------

__global__ void zero_all_kernel() {
    int i = blockIdx.x * blockDim.x + threadIdx.x;
    if (i < NN) g_deg[i] = 0;
    if (i < NBUK) { g_bcnt[i] = 0; g_bfill[i] = 0; }
}

__global__ void count_deg_kernel(const int* __restrict__ col32) {
    int e = blockIdx.x * blockDim.x + threadIdx.x;
    if (e < EE) {
        int c = col32[e];
        if (c < 0 || c >= NN) c = 0;
        atomicAdd(&g_deg[c], 1);           // return unused -> RED
    }
}

__global__ void count_bkt_kernel(const int* __restrict__ row32) {
    int e = blockIdx.x * blockDim.x + threadIdx.x;
    if (e < EE) {
        int r = row32[e];
        if (r < 0 || r >= NN) r = 0;
        atomicAdd(&g_bcnt[r >> BSH], 1);   // return unused -> RED
    }
}

__global__ void dinv_kernel() {
    int i = blockIdx.x * blockDim.x + threadIdx.x;
    if (i < NN) {
        int d = g_deg[i];
        g_dinv[i] = (d > 0) ? rsqrtf((float)d) : 0.0f;
    }
}

// exclusive scan of g_bcnt (3125) -> g_bptr, 3 small kernels
__global__ void bscanA_kernel() {
    __shared__ int s[SCB];
    int tid = threadIdx.x;
    int gid = blockIdx.x * SCB + tid;
    int v = (gid < NBUK) ? g_bcnt[gid] : 0;
    s[tid] = v;
    __syncthreads();
    #pragma unroll
    for (int off = 1; off < SCB; off <<= 1) {
        int t = (tid >= off) ? s[tid - off] : 0;
        __syncthreads();
        s[tid] += t;
        __syncthreads();
    }
    if (gid < NBUK) g_bptr[gid] = s[tid] - v;
    if (tid == SCB - 1) g_sbs[blockIdx.x] = s[tid];
}

__global__ void bscanB_kernel() {
    // single block, NSB=13 entries: serial scan by thread 0 (trivial size)
    if (threadIdx.x == 0) {
        int acc = 0;
        for (int b = 0; b < NSB; b++) {
            int v = g_sbs[b];
            g_sbs[b] = acc;
            acc += v;
        }
        g_bptr[NBUK] = acc;
    }
}

__global__ void bscanC_kernel() {
    int gid = blockIdx.x * SCB + threadIdx.x;
    if (gid < NBUK) g_bptr[gid] += g_sbs[blockIdx.x];
}

// counting-sort fill into source-buckets
__global__ void fill_kernel(const int* __restrict__ row32,
                            const int* __restrict__ col32) {
    int e = blockIdx.x * blockDim.x + threadIdx.x;
    if (e < EE) {
        int r = row32[e];
        int c = col32[e];
        if (r < 0 || r >= NN) r = 0;
        if (c < 0 || c >= NN) c = 0;
        float nrm = g_dinv[r] * g_dinv[c];
        int bk = r >> BSH;
        int pos = g_bptr[bk] + atomicAdd(&g_bfill[bk], 1);
        g_eb[pos] = make_int4(r, c, __float_as_int(nrm), 0);
    }
}

// out = emb ; xa = emb   (float4)
__global__ void init_kernel(const float* __restrict__ emb, float* __restrict__ out) {
    int i = blockIdx.x * blockDim.x + threadIdx.x;
    if (i < ND4) {
        float4 v = reinterpret_cast<const float4*>(emb)[i];
        reinterpret_cast<float4*>(g_xa)[i] = v;
        reinterpret_cast<float4*>(out)[i] = v;
    }
}

__global__ void zero_x_kernel(int which) {
    int i = blockIdx.x * blockDim.x + threadIdx.x;
    if (i < ND4) {
        float4 z = make_float4(0.f, 0.f, 0.f, 0.f);
        if (which == 0) reinterpret_cast<float4*>(g_xb)[i] = z;
        else            reinterpret_cast<float4*>(g_xa)[i] = z;
    }
}

// out = (out + x) * scale  (float4)
__global__ void accum_kernel(float* __restrict__ out, int which, float scale) {
    int i = blockIdx.x * blockDim.x + threadIdx.x;
    if (i < ND4) {
        float4 xv = (which == 0) ? reinterpret_cast<const float4*>(g_xb)[i]
                                 : reinterpret_cast<const float4*>(g_xa)[i];
        float4 ov = reinterpret_cast<const float4*>(out)[i];
        ov.x = (ov.x + xv.x) * scale;
        ov.y = (ov.y + xv.y) * scale;
        ov.z = (ov.z + xv.z) * scale;
        ov.w = (ov.w + xv.w) * scale;
        reinterpret_cast<float4*>(out)[i] = ov;
    }
}

// ---------------- bucketed SMEM-tile scatter ----------------
// One block per source bucket: stage 32 rows (8KB) in SMEM, stream the
// bucket's edges: LDS.128 + RED.128 per edge-chunk. Gather L2 reads drop 32x.
template <int DIR>
__global__ __launch_bounds__(256) void scatter_kernel() {
    const float* xin  = DIR == 0 ? g_xa : g_xb;
    float*       xout = DIR == 0 ? g_xb : g_xa;

    __shared__ float4 tile[BSZ * 16];   // 32 rows x 64 floats = 8KB

    int b = blockIdx.x;
    int tid = threadIdx.x;
    int base = b << BSH;

    // stage tile (coalesced: 512 float4 by 256 threads)
    const float4* xin4 = reinterpret_cast<const float4*>(xin);
    #pragma unroll
    for (int i = 0; i < 2; i++) {
        int t = tid + i * 256;
        tile[t] = xin4[(size_t)base * 16 + t];
    }
    __syncthreads();

    int es = g_bptr[b];
    int ee = g_bptr[b + 1];

    for (int k = es * 16 + tid; k < ee * 16; k += 256) {
        int e = k >> 4;
        int c = k & 15;
        int4 ed = __ldg(&g_eb[e]);             // 16 threads same e -> broadcast
        float nm = __int_as_float(ed.z);
        float4 v = tile[((ed.x - base) << 4) + c];
        v.x *= nm; v.y *= nm; v.z *= nm; v.w *= nm;
        float4* dst = reinterpret_cast<float4*>(xout + (size_t)ed.y * DD) + c;
        asm volatile("red.global.add.v4.f32 [%0], {%1,%2,%3,%4};"
                     :: "l"(dst), "f"(v.x), "f"(v.y), "f"(v.z), "f"(v.w)
                     : "memory");
    }
}

// ---------------- launch ----------------

extern "C" void kernel_launch(void* const* d_in, const int* in_sizes, int n_in,
                              void* d_out, int out_size) {
    const float* emb = (const float*)d_in[0];
    const int* edge = (const int*)d_in[1];   // [2, EE] int32
    const int* row32 = edge;
    const int* col32 = edge + EE;
    float* out = (float*)d_out;

    const int T = 256;
    int gN  = (NN + T - 1) / T;
    int gE  = (EE + T - 1) / T;
    int gV  = (ND4 + T - 1) / T;

    // preprocessing + bucketed edge-list build
    zero_all_kernel<<<gN, T>>>();
    count_deg_kernel<<<gE, T>>>(col32);
    count_bkt_kernel<<<gE, T>>>(row32);
    dinv_kernel<<<gN, T>>>();
    bscanA_kernel<<<NSB, SCB>>>();
    bscanB_kernel<<<1, 32>>>();
    bscanC_kernel<<<NSB, SCB>>>();
    fill_kernel<<<gE, T>>>(row32, col32);

    init_kernel<<<gV, T>>>(emb, out);

    // layer 0: xa -> xb
    zero_x_kernel<<<gV, T>>>(0);
    scatter_kernel<0><<<NBUK, T>>>();
    accum_kernel<<<gV, T>>>(out, 0, 1.0f);

    // layer 1: xb -> xa
    zero_x_kernel<<<gV, T>>>(1);
    scatter_kernel<1><<<NBUK, T>>>();
    accum_kernel<<<gV, T>>>(out, 1, 1.0f);

    // layer 2: xa -> xb (fold /4 into final accumulate)
    zero_x_kernel<<<gV, T>>>(0);
    scatter_kernel<0><<<NBUK, T>>>();
    accum_kernel<<<gV, T>>>(out, 0, 0.25f);
}

// round 14
// speedup vs baseline: 1.0106x; 1.0106x over previous
#include <cuda_runtime.h>
#include <cstdint>

#define NN 100000
#define EE 3200000
#define DD 64
#define ND4 (NN * DD / 4)        // 1,600,000 float4
#define BSH 5                    // 32 nodes per bucket
#define BSZ 32
#define NBUK (NN / BSZ)          // 3125 exactly
#define SCB 256
#define NSB ((NBUK + SCB - 1) / SCB)   // 13

// Scratch (static __device__ arrays; no allocation allowed)
__device__ int   g_deg[NN];
__device__ float g_dinv[NN];
__device__ int   g_bcnt[NBUK];
__device__ int   g_bfill[NBUK];
__device__ int   g_bptr[NBUK + 1];
__device__ int   g_sbs[NSB];
__device__ __align__(16) int2  g_eb[EE];     // bucketed: {(srcoff<<17)|col, bitcast(norm)}
__device__ __align__(16) float g_xa[NN * DD];
__device__ __align__(16) float g_xb[NN * DD];

// ---------------- preprocessing ----------------

__global__ void zero_all_kernel() {
    int i = blockIdx.x * blockDim.x + threadIdx.x;
    if (i < NN) g_deg[i] = 0;
    if (i < NBUK) { g_bcnt[i] = 0; g_bfill[i] = 0; }
}

// fused: in-degree histogram (by col) + bucket histogram (by row), one pass
__global__ void count_both_kernel(const int* __restrict__ row32,
                                  const int* __restrict__ col32) {
    int e = blockIdx.x * blockDim.x + threadIdx.x;
    if (e < EE) {
        int c = col32[e];
        int r = row32[e];
        if (c < 0 || c >= NN) c = 0;
        if (r < 0 || r >= NN) r = 0;
        atomicAdd(&g_deg[c], 1);           // return unused -> RED
        atomicAdd(&g_bcnt[r >> BSH], 1);   // return unused -> RED
    }
}

__global__ void dinv_kernel() {
    int i = blockIdx.x * blockDim.x + threadIdx.x;
    if (i < NN) {
        int d = g_deg[i];
        g_dinv[i] = (d > 0) ? rsqrtf((float)d) : 0.0f;
    }
}

// exclusive scan of g_bcnt (3125) -> g_bptr
__global__ void bscanA_kernel() {
    __shared__ int s[SCB];
    int tid = threadIdx.x;
    int gid = blockIdx.x * SCB + tid;
    int v = (gid < NBUK) ? g_bcnt[gid] : 0;
    s[tid] = v;
    __syncthreads();
    #pragma unroll
    for (int off = 1; off < SCB; off <<= 1) {
        int t = (tid >= off) ? s[tid - off] : 0;
        __syncthreads();
        s[tid] += t;
        __syncthreads();
    }
    if (gid < NBUK) g_bptr[gid] = s[tid] - v;
    if (tid == SCB - 1) g_sbs[blockIdx.x] = s[tid];
}

__global__ void bscanB_kernel() {
    if (threadIdx.x == 0) {
        int acc = 0;
        for (int b = 0; b < NSB; b++) {
            int v = g_sbs[b];
            g_sbs[b] = acc;
            acc += v;
        }
        g_bptr[NBUK] = acc;
    }
}

__global__ void bscanC_kernel() {
    int gid = blockIdx.x * SCB + threadIdx.x;
    if (gid < NBUK) g_bptr[gid] += g_sbs[blockIdx.x];
}

// counting-sort fill into source buckets; packed 8B payload
__global__ void fill_kernel(const int* __restrict__ row32,
                            const int* __restrict__ col32) {
    int e = blockIdx.x * blockDim.x + threadIdx.x;
    if (e < EE) {
        int r = row32[e];
        int c = col32[e];
        if (r < 0 || r >= NN) r = 0;
        if (c < 0 || c >= NN) c = 0;
        float nrm = g_dinv[r] * g_dinv[c];
        int bk = r >> BSH;
        int so = r & (BSZ - 1);
        int pos = g_bptr[bk] + atomicAdd(&g_bfill[bk], 1);
        g_eb[pos] = make_int2((so << 17) | c, __float_as_int(nrm));
    }
}

// out = emb ; xa = emb   (float4)
__global__ void init_kernel(const float* __restrict__ emb, float* __restrict__ out) {
    int i = blockIdx.x * blockDim.x + threadIdx.x;
    if (i < ND4) {
        float4 v = reinterpret_cast<const float4*>(emb)[i];
        reinterpret_cast<float4*>(g_xa)[i] = v;
        reinterpret_cast<float4*>(out)[i] = v;
    }
}

__global__ void zero_x_kernel(int which) {
    int i = blockIdx.x * blockDim.x + threadIdx.x;
    if (i < ND4) {
        float4 z = make_float4(0.f, 0.f, 0.f, 0.f);
        if (which == 0) reinterpret_cast<float4*>(g_xb)[i] = z;
        else            reinterpret_cast<float4*>(g_xa)[i] = z;
    }
}

// out = (out + x) * scale  (float4)
__global__ void accum_kernel(float* __restrict__ out, int which, float scale) {
    int i = blockIdx.x * blockDim.x + threadIdx.x;
    if (i < ND4) {
        float4 xv = (which == 0) ? reinterpret_cast<const float4*>(g_xb)[i]
                                 : reinterpret_cast<const float4*>(g_xa)[i];
        float4 ov = reinterpret_cast<const float4*>(out)[i];
        ov.x = (ov.x + xv.x) * scale;
        ov.y = (ov.y + xv.y) * scale;
        ov.z = (ov.z + xv.z) * scale;
        ov.w = (ov.w + xv.w) * scale;
        reinterpret_cast<float4*>(out)[i] = ov;
    }
}

// ---------------- bucketed SMEM-tile scatter (R13 structure, packed payload) ----------------
template <int DIR>
__global__ __launch_bounds__(256) void scatter_kernel() {
    const float* xin  = DIR == 0 ? g_xa : g_xb;
    float*       xout = DIR == 0 ? g_xb : g_xa;

    __shared__ float4 tile[BSZ * 16];   // 32 rows x 64 floats = 8KB

    int b = blockIdx.x;
    int tid = threadIdx.x;

    // stage tile (coalesced: 512 float4 by 256 threads)
    const float4* xin4 = reinterpret_cast<const float4*>(xin);
    size_t base16 = (size_t)(b << BSH) * 16;
    tile[tid]       = xin4[base16 + tid];
    tile[tid + 256] = xin4[base16 + tid + 256];
    __syncthreads();

    int es = g_bptr[b];
    int ee = g_bptr[b + 1];

    for (int k = es * 16 + tid; k < ee * 16; k += 256) {
        int e = k >> 4;
        int c = k & 15;
        int2 ed = __ldg(&g_eb[e]);              // 16 threads same e -> broadcast
        int col = ed.x & 0x1FFFF;
        int so  = ed.x >> 17;
        float nm = __int_as_float(ed.y);
        float4 v = tile[(so << 4) + c];
        v.x *= nm; v.y *= nm; v.z *= nm; v.w *= nm;
        float4* dst = reinterpret_cast<float4*>(xout + (size_t)col * DD) + c;
        asm volatile("red.global.add.v4.f32 [%0], {%1,%2,%3,%4};"
                     :: "l"(dst), "f"(v.x), "f"(v.y), "f"(v.z), "f"(v.w)
                     : "memory");
    }
}

// ---------------- launch ----------------

extern "C" void kernel_launch(void* const* d_in, const int* in_sizes, int n_in,
                              void* d_out, int out_size) {
    const float* emb = (const float*)d_in[0];
    const int* edge = (const int*)d_in[1];   // [2, EE] int32
    const int* row32 = edge;
    const int* col32 = edge + EE;
    float* out = (float*)d_out;

    const int T = 256;
    int gN  = (NN + T - 1) / T;
    int gE  = (EE + T - 1) / T;
    int gV  = (ND4 + T - 1) / T;

    // preprocessing + bucketed edge-list build
    zero_all_kernel<<<gN, T>>>();
    count_both_kernel<<<gE, T>>>(row32, col32);
    dinv_kernel<<<gN, T>>>();
    bscanA_kernel<<<NSB, SCB>>>();
    bscanB_kernel<<<1, 32>>>();
    bscanC_kernel<<<NSB, SCB>>>();
    fill_kernel<<<gE, T>>>(row32, col32);

    init_kernel<<<gV, T>>>(emb, out);

    // layer 0: xa -> xb
    zero_x_kernel<<<gV, T>>>(0);
    scatter_kernel<0><<<NBUK, T>>>();
    accum_kernel<<<gV, T>>>(out, 0, 1.0f);

    // layer 1: xb -> xa
    zero_x_kernel<<<gV, T>>>(1);
    scatter_kernel<1><<<NBUK, T>>>();
    accum_kernel<<<gV, T>>>(out, 1, 1.0f);

    // layer 2: xa -> xb (fold /4 into final accumulate)
    zero_x_kernel<<<gV, T>>>(0);
    scatter_kernel<0><<<NBUK, T>>>();
    accum_kernel<<<gV, T>>>(out, 0, 0.25f);
}

// round 15
// speedup vs baseline: 1.3936x; 1.3789x over previous
#include <cuda_runtime.h>
#include <cstdint>

#define NN 100000
#define EE 3200000
#define DD 64
#define ND4 (NN * DD / 4)        // 1,600,000 float4
#define NPAIR (EE / 2)           // 1,600,000 pairs
#define PRIME 999983LL           // coprime with NPAIR (no factor 2 or 5)
#define SCAN_B 256
#define NBLK ((NN + SCAN_B - 1) / SCAN_B)   // 391

// Static scratch (no allocation allowed)
__device__ int   g_deg[NN];
__device__ float g_dinv[NN];
__device__ int   g_ptr[NN + 1];
__device__ int   g_bsum[NBLK];
__device__ int   g_boff[NBLK];
__device__ int   g_fill[NN];
__device__ __align__(16) int2 g_sn[EE];      // target-sorted: {src, bitcast(norm)}
__device__ __align__(16) int  g_tg[EE];      // target-sorted: target
__device__ __align__(16) float g_xa[NN * DD];
__device__ __align__(16) float g_xb[NN * DD];

// ---------------- build: target-sorted edge list ----------------

__global__ void zero_counts_kernel() {
    int i = blockIdx.x * blockDim.x + threadIdx.x;
    if (i < NN) { g_deg[i] = 0; g_fill[i] = 0; }
}

__global__ void count_deg_kernel(const int* __restrict__ col32) {
    int e = blockIdx.x * blockDim.x + threadIdx.x;
    if (e < EE) {
        int c = col32[e];
        if (c >= 0 && c < NN) atomicAdd(&g_deg[c], 1);   // return unused -> RED
    }
}

__global__ void dinv_kernel() {
    int i = blockIdx.x * blockDim.x + threadIdx.x;
    if (i < NN) {
        int d = g_deg[i];
        g_dinv[i] = (d > 0) ? rsqrtf((float)d) : 0.0f;
    }
}

__global__ void scan1_kernel() {
    __shared__ int s[SCAN_B];
    int tid = threadIdx.x;
    int gid = blockIdx.x * SCAN_B + tid;
    int v = (gid < NN) ? g_deg[gid] : 0;
    s[tid] = v;
    __syncthreads();
    #pragma unroll
    for (int off = 1; off < SCAN_B; off <<= 1) {
        int t = (tid >= off) ? s[tid - off] : 0;
        __syncthreads();
        s[tid] += t;
        __syncthreads();
    }
    if (gid < NN) g_ptr[gid] = s[tid] - v;
    if (tid == SCAN_B - 1) g_bsum[blockIdx.x] = s[tid];
}

__global__ void scan2_kernel() {
    __shared__ int s[512];
    int tid = threadIdx.x;
    int v = (tid < NBLK) ? g_bsum[tid] : 0;
    s[tid] = v;
    __syncthreads();
    #pragma unroll
    for (int off = 1; off < 512; off <<= 1) {
        int t = (tid >= off) ? s[tid - off] : 0;
        __syncthreads();
        s[tid] += t;
        __syncthreads();
    }
    if (tid < NBLK) g_boff[tid] = s[tid] - v;
    if (tid == NBLK - 1) g_ptr[NN] = s[tid];
}

__global__ void scan3_kernel() {
    int gid = blockIdx.x * SCAN_B + threadIdx.x;
    if (gid < NN) g_ptr[gid] += g_boff[blockIdx.x];
}

__global__ void fill_kernel(const int* __restrict__ row32,
                            const int* __restrict__ col32) {
    int e = blockIdx.x * blockDim.x + threadIdx.x;
    if (e < EE) {
        int r = row32[e];
        int c = col32[e];
        if (r < 0 || r >= NN) r = 0;
        if (c < 0 || c >= NN) c = 0;
        float nrm = g_dinv[r] * g_dinv[c];
        int pos = g_ptr[c] + atomicAdd(&g_fill[c], 1);
        g_sn[pos] = make_int2(r, __float_as_int(nrm));
        g_tg[pos] = c;
    }
}

// ---------------- elementwise (R12, vectorized) ----------------

// out = emb ; xa = emb
__global__ void init_kernel(const float* __restrict__ emb, float* __restrict__ out) {
    int i = blockIdx.x * blockDim.x + threadIdx.x;
    if (i < ND4) {
        float4 v = reinterpret_cast<const float4*>(emb)[i];
        reinterpret_cast<float4*>(g_xa)[i] = v;
        reinterpret_cast<float4*>(out)[i] = v;
    }
}

__global__ void zero_x_kernel(int which) {
    int i = blockIdx.x * blockDim.x + threadIdx.x;
    if (i < ND4) {
        float4 z = make_float4(0.f, 0.f, 0.f, 0.f);
        if (which == 0) reinterpret_cast<float4*>(g_xb)[i] = z;
        else            reinterpret_cast<float4*>(g_xa)[i] = z;
    }
}

// out = (out + x) * scale
__global__ void accum_kernel(float* __restrict__ out, int which, float scale) {
    int i = blockIdx.x * blockDim.x + threadIdx.x;
    if (i < ND4) {
        float4 xv = (which == 0) ? reinterpret_cast<const float4*>(g_xb)[i]
                                 : reinterpret_cast<const float4*>(g_xa)[i];
        float4 ov = reinterpret_cast<const float4*>(out)[i];
        ov.x = (ov.x + xv.x) * scale;
        ov.y = (ov.y + xv.y) * scale;
        ov.z = (ov.z + xv.z) * scale;
        ov.w = (ov.w + xv.w) * scale;
        reinterpret_cast<float4*>(out)[i] = ov;
    }
}

// ---------------- permuted pair-merged scatter ----------------
// Thread-group (16 threads) p processes sorted pair q = (p*PRIME) mod NPAIR:
// edges 2q, 2q+1 share a target with p~0.97 -> merged into ONE red.v4.
// The permutation spreads same-target REDs far apart in time, avoiding
// LTS same-address serialization (the R5 failure mode).
template <int DIR>
__global__ __launch_bounds__(256) void pscatter_kernel() {
    const float* xin  = DIR == 0 ? g_xa : g_xb;
    float*       xout = DIR == 0 ? g_xb : g_xa;

    int gid = blockIdx.x * 256 + threadIdx.x;   // < 25.6M, fits int
    int c = gid & 15;
    int p = gid >> 4;
    if (p >= NPAIR) return;
    int q = (int)(((long long)p * PRIME) % NPAIR);

    int4 sn = __ldg(reinterpret_cast<const int4*>(g_sn) + q);  // {src0,n0,src1,n1}
    int2 tg = __ldg(reinterpret_cast<const int2*>(g_tg) + q);  // {t0,t1}
    float n0 = __int_as_float(sn.y);
    float n1 = __int_as_float(sn.w);

    float4 v0 = __ldg(reinterpret_cast<const float4*>(xin + (size_t)sn.x * DD) + c);
    float4 v1 = __ldg(reinterpret_cast<const float4*>(xin + (size_t)sn.z * DD) + c);

    float4 m0, m1;
    m0.x = n0 * v0.x; m0.y = n0 * v0.y; m0.z = n0 * v0.z; m0.w = n0 * v0.w;
    m1.x = n1 * v1.x; m1.y = n1 * v1.y; m1.z = n1 * v1.z; m1.w = n1 * v1.w;

    float4* d0 = reinterpret_cast<float4*>(xout + (size_t)tg.x * DD) + c;
    if (tg.x == tg.y) {
        m0.x += m1.x; m0.y += m1.y; m0.z += m1.z; m0.w += m1.w;
        asm volatile("red.global.add.v4.f32 [%0], {%1,%2,%3,%4};"
                     :: "l"(d0), "f"(m0.x), "f"(m0.y), "f"(m0.z), "f"(m0.w)
                     : "memory");
    } else {
        asm volatile("red.global.add.v4.f32 [%0], {%1,%2,%3,%4};"
                     :: "l"(d0), "f"(m0.x), "f"(m0.y), "f"(m0.z), "f"(m0.w)
                     : "memory");
        float4* d1 = reinterpret_cast<float4*>(xout + (size_t)tg.y * DD) + c;
        asm volatile("red.global.add.v4.f32 [%0], {%1,%2,%3,%4};"
                     :: "l"(d1), "f"(m1.x), "f"(m1.y), "f"(m1.z), "f"(m1.w)
                     : "memory");
    }
}

// ---------------- launch ----------------

extern "C" void kernel_launch(void* const* d_in, const int* in_sizes, int n_in,
                              void* d_out, int out_size) {
    const float* emb = (const float*)d_in[0];
    const int* edge = (const int*)d_in[1];   // [2, EE] int32
    const int* row32 = edge;
    const int* col32 = edge + EE;
    float* out = (float*)d_out;

    const int T = 256;
    int gN  = (NN + T - 1) / T;
    int gE  = (EE + T - 1) / T;
    int gV  = (ND4 + T - 1) / T;
    int gS  = (NPAIR * 16 + T - 1) / T;      // 100,000 blocks

    // build target-sorted edge list
    zero_counts_kernel<<<gN, T>>>();
    count_deg_kernel<<<gE, T>>>(col32);
    dinv_kernel<<<gN, T>>>();
    scan1_kernel<<<NBLK, SCAN_B>>>();
    scan2_kernel<<<1, 512>>>();
    scan3_kernel<<<NBLK, SCAN_B>>>();
    fill_kernel<<<gE, T>>>(row32, col32);

    init_kernel<<<gV, T>>>(emb, out);

    // layer 0: xa -> xb
    zero_x_kernel<<<gV, T>>>(0);
    pscatter_kernel<0><<<gS, T>>>();
    accum_kernel<<<gV, T>>>(out, 0, 1.0f);

    // layer 1: xb -> xa
    zero_x_kernel<<<gV, T>>>(1);
    pscatter_kernel<1><<<gS, T>>>();
    accum_kernel<<<gV, T>>>(out, 1, 1.0f);

    // layer 2: xa -> xb (fold /4 into final accumulate)
    zero_x_kernel<<<gV, T>>>(0);
    pscatter_kernel<0><<<gS, T>>>();
    accum_kernel<<<gV, T>>>(out, 0, 0.25f);
}

// round 16
// speedup vs baseline: 1.6299x; 1.1696x over previous
#include <cuda_runtime.h>
#include <cstdint>

#define NN 100000
#define EE 3200000
#define DD 64
#define ND4 (NN * DD / 4)        // 1,600,000 float4
#define NQUAD (EE / 4)           // 800,000 quads
#define PRIME 999983LL           // coprime with NQUAD (odd, not div by 5)
#define SCAN_B 256
#define NBLK ((NN + SCAN_B - 1) / SCAN_B)   // 391

// Static scratch (no allocation allowed)
__device__ int   g_deg[NN];
__device__ float g_dinv[NN];
__device__ int   g_ptr[NN + 1];
__device__ int   g_bsum[NBLK];
__device__ int   g_boff[NBLK];
__device__ int   g_fill[NN];
__device__ __align__(16) int2 g_sn[EE];      // target-sorted: {src, bitcast(norm)}
__device__ __align__(16) int  g_tg[EE];      // target-sorted: target
__device__ __align__(16) float g_xa[NN * DD];
__device__ __align__(16) float g_xb[NN * DD];

// ---------------- build: target-sorted edge list (R15 verbatim) ----------------

__global__ void zero_counts_kernel() {
    int i = blockIdx.x * blockDim.x + threadIdx.x;
    if (i < NN) { g_deg[i] = 0; g_fill[i] = 0; }
}

__global__ void count_deg_kernel(const int* __restrict__ col32) {
    int e = blockIdx.x * blockDim.x + threadIdx.x;
    if (e < EE) {
        int c = col32[e];
        if (c >= 0 && c < NN) atomicAdd(&g_deg[c], 1);   // return unused -> RED
    }
}

__global__ void dinv_kernel() {
    int i = blockIdx.x * blockDim.x + threadIdx.x;
    if (i < NN) {
        int d = g_deg[i];
        g_dinv[i] = (d > 0) ? rsqrtf((float)d) : 0.0f;
    }
}

__global__ void scan1_kernel() {
    __shared__ int s[SCAN_B];
    int tid = threadIdx.x;
    int gid = blockIdx.x * SCAN_B + tid;
    int v = (gid < NN) ? g_deg[gid] : 0;
    s[tid] = v;
    __syncthreads();
    #pragma unroll
    for (int off = 1; off < SCAN_B; off <<= 1) {
        int t = (tid >= off) ? s[tid - off] : 0;
        __syncthreads();
        s[tid] += t;
        __syncthreads();
    }
    if (gid < NN) g_ptr[gid] = s[tid] - v;
    if (tid == SCAN_B - 1) g_bsum[blockIdx.x] = s[tid];
}

__global__ void scan2_kernel() {
    __shared__ int s[512];
    int tid = threadIdx.x;
    int v = (tid < NBLK) ? g_bsum[tid] : 0;
    s[tid] = v;
    __syncthreads();
    #pragma unroll
    for (int off = 1; off < 512; off <<= 1) {
        int t = (tid >= off) ? s[tid - off] : 0;
        __syncthreads();
        s[tid] += t;
        __syncthreads();
    }
    if (tid < NBLK) g_boff[tid] = s[tid] - v;
    if (tid == NBLK - 1) g_ptr[NN] = s[tid];
}

__global__ void scan3_kernel() {
    int gid = blockIdx.x * SCAN_B + threadIdx.x;
    if (gid < NN) g_ptr[gid] += g_boff[blockIdx.x];
}

__global__ void fill_kernel(const int* __restrict__ row32,
                            const int* __restrict__ col32) {
    int e = blockIdx.x * blockDim.x + threadIdx.x;
    if (e < EE) {
        int r = row32[e];
        int c = col32[e];
        if (r < 0 || r >= NN) r = 0;
        if (c < 0 || c >= NN) c = 0;
        float nrm = g_dinv[r] * g_dinv[c];
        int pos = g_ptr[c] + atomicAdd(&g_fill[c], 1);
        g_sn[pos] = make_int2(r, __float_as_int(nrm));
        g_tg[pos] = c;
    }
}

// ---------------- elementwise (vectorized, R12/R15 verbatim) ----------------

__global__ void init_kernel(const float* __restrict__ emb, float* __restrict__ out) {
    int i = blockIdx.x * blockDim.x + threadIdx.x;
    if (i < ND4) {
        float4 v = reinterpret_cast<const float4*>(emb)[i];
        reinterpret_cast<float4*>(g_xa)[i] = v;
        reinterpret_cast<float4*>(out)[i] = v;
    }
}

__global__ void zero_x_kernel(int which) {
    int i = blockIdx.x * blockDim.x + threadIdx.x;
    if (i < ND4) {
        float4 z = make_float4(0.f, 0.f, 0.f, 0.f);
        if (which == 0) reinterpret_cast<float4*>(g_xb)[i] = z;
        else            reinterpret_cast<float4*>(g_xa)[i] = z;
    }
}

__global__ void accum_kernel(float* __restrict__ out, int which, float scale) {
    int i = blockIdx.x * blockDim.x + threadIdx.x;
    if (i < ND4) {
        float4 xv = (which == 0) ? reinterpret_cast<const float4*>(g_xb)[i]
                                 : reinterpret_cast<const float4*>(g_xa)[i];
        float4 ov = reinterpret_cast<const float4*>(out)[i];
        ov.x = (ov.x + xv.x) * scale;
        ov.y = (ov.y + xv.y) * scale;
        ov.z = (ov.z + xv.z) * scale;
        ov.w = (ov.w + xv.w) * scale;
        reinterpret_cast<float4*>(out)[i] = ov;
    }
}

// ---------------- permuted quad-merged scatter ----------------
// 16-thread group p processes sorted quad q = (p*PRIME) mod NQUAD:
// edges 4q..4q+3 usually share one target (p~0.91) -> typically ONE red.v4.
// Coprime-stride permutation keeps same-target REDs temporally spread.
__device__ __forceinline__ void red4(float4* dst, float4 v) {
    asm volatile("red.global.add.v4.f32 [%0], {%1,%2,%3,%4};"
                 :: "l"(dst), "f"(v.x), "f"(v.y), "f"(v.z), "f"(v.w)
                 : "memory");
}

template <int DIR>
__global__ __launch_bounds__(256) void qscatter_kernel() {
    const float* xin  = DIR == 0 ? g_xa : g_xb;
    float*       xout = DIR == 0 ? g_xb : g_xa;

    int gid = blockIdx.x * 256 + threadIdx.x;   // < 12.8M, fits int
    int c = gid & 15;
    int p = gid >> 4;
    if (p >= NQUAD) return;
    int q = (int)(((long long)p * PRIME) % NQUAD);

    const int4* sn4 = reinterpret_cast<const int4*>(g_sn);
    int4 sA = __ldg(sn4 + 2 * q);               // {src0,n0,src1,n1}
    int4 sB = __ldg(sn4 + 2 * q + 1);           // {src2,n2,src3,n3}
    int4 tg = __ldg(reinterpret_cast<const int4*>(g_tg) + q);  // {t0,t1,t2,t3}

    // issue all 4 gathers up front (max MLP)
    const float4* x4 = reinterpret_cast<const float4*>(xin);
    float4 v0 = __ldg(x4 + (size_t)sA.x * 16 + c);
    float4 v1 = __ldg(x4 + (size_t)sA.z * 16 + c);
    float4 v2 = __ldg(x4 + (size_t)sB.x * 16 + c);
    float4 v3 = __ldg(x4 + (size_t)sB.z * 16 + c);

    float n0 = __int_as_float(sA.y), n1 = __int_as_float(sA.w);
    float n2 = __int_as_float(sB.y), n3 = __int_as_float(sB.w);

    float4 m0 = make_float4(n0*v0.x, n0*v0.y, n0*v0.z, n0*v0.w);
    float4 m1 = make_float4(n1*v1.x, n1*v1.y, n1*v1.z, n1*v1.w);
    float4 m2 = make_float4(n2*v2.x, n2*v2.y, n2*v2.z, n2*v2.w);
    float4 m3 = make_float4(n3*v3.x, n3*v3.y, n3*v3.z, n3*v3.w);

    float4* out4 = reinterpret_cast<float4*>(xout);

    // run-merge (uniform across the 16-thread group; sorted so equal targets adjacent)
    float4 acc = m0;
    int cur = tg.x;
    if (tg.y == cur) { acc.x += m1.x; acc.y += m1.y; acc.z += m1.z; acc.w += m1.w; }
    else { red4(out4 + (size_t)cur * 16 + c, acc); cur = tg.y; acc = m1; }
    if (tg.z == cur) { acc.x += m2.x; acc.y += m2.y; acc.z += m2.z; acc.w += m2.w; }
    else { red4(out4 + (size_t)cur * 16 + c, acc); cur = tg.z; acc = m2; }
    if (tg.w == cur) { acc.x += m3.x; acc.y += m3.y; acc.z += m3.z; acc.w += m3.w; }
    else { red4(out4 + (size_t)cur * 16 + c, acc); cur = tg.w; acc = m3; }
    red4(out4 + (size_t)cur * 16 + c, acc);
}

// ---------------- launch ----------------

extern "C" void kernel_launch(void* const* d_in, const int* in_sizes, int n_in,
                              void* d_out, int out_size) {
    const float* emb = (const float*)d_in[0];
    const int* edge = (const int*)d_in[1];   // [2, EE] int32
    const int* row32 = edge;
    const int* col32 = edge + EE;
    float* out = (float*)d_out;

    const int T = 256;
    int gN  = (NN + T - 1) / T;
    int gE  = (EE + T - 1) / T;
    int gV  = (ND4 + T - 1) / T;
    int gS  = (NQUAD * 16 + T - 1) / T;      // 50,000 blocks

    // build target-sorted edge list
    zero_counts_kernel<<<gN, T>>>();
    count_deg_kernel<<<gE, T>>>(col32);
    dinv_kernel<<<gN, T>>>();
    scan1_kernel<<<NBLK, SCAN_B>>>();
    scan2_kernel<<<1, 512>>>();
    scan3_kernel<<<NBLK, SCAN_B>>>();
    fill_kernel<<<gE, T>>>(row32, col32);

    init_kernel<<<gV, T>>>(emb, out);

    // layer 0: xa -> xb
    zero_x_kernel<<<gV, T>>>(0);
    qscatter_kernel<0><<<gS, T>>>();
    accum_kernel<<<gV, T>>>(out, 0, 1.0f);

    // layer 1: xb -> xa
    zero_x_kernel<<<gV, T>>>(1);
    qscatter_kernel<1><<<gS, T>>>();
    accum_kernel<<<gV, T>>>(out, 1, 1.0f);

    // layer 2: xa -> xb (fold /4 into final accumulate)
    zero_x_kernel<<<gV, T>>>(0);
    qscatter_kernel<0><<<gS, T>>>();
    accum_kernel<<<gV, T>>>(out, 0, 0.25f);
}

// round 17
// speedup vs baseline: 1.7153x; 1.0524x over previous
#include <cuda_runtime.h>
#include <cstdint>

#define NN 100000
#define EE 3200000
#define DD 64
#define ND4 (NN * DD / 4)        // 1,600,000 float4
#define NOCT (EE / 8)            // 400,000 octs
#define PRIME 999983LL           // coprime with NOCT (odd, not div by 5)
#define SCAN_B 256
#define NBLK ((NN + SCAN_B - 1) / SCAN_B)   // 391

// Static scratch (no allocation allowed)
__device__ int   g_deg[NN];
__device__ float g_dinv[NN];
__device__ int   g_ptr[NN + 1];
__device__ int   g_bsum[NBLK];
__device__ int   g_boff[NBLK];
__device__ int   g_fill[NN];
__device__ __align__(16) int2 g_sn[EE];      // target-sorted: {src, bitcast(norm)}
__device__ __align__(16) int  g_tg[EE];      // target-sorted: target
__device__ __align__(16) float g_xa[NN * DD];
__device__ __align__(16) float g_xb[NN * DD];

// ---------------- build: target-sorted edge list (R15/R16 verbatim) ----------------

__global__ void zero_counts_kernel() {
    int i = blockIdx.x * blockDim.x + threadIdx.x;
    if (i < NN) { g_deg[i] = 0; g_fill[i] = 0; }
}

__global__ void count_deg_kernel(const int* __restrict__ col32) {
    int e = blockIdx.x * blockDim.x + threadIdx.x;
    if (e < EE) {
        int c = col32[e];
        if (c >= 0 && c < NN) atomicAdd(&g_deg[c], 1);   // return unused -> RED
    }
}

__global__ void dinv_kernel() {
    int i = blockIdx.x * blockDim.x + threadIdx.x;
    if (i < NN) {
        int d = g_deg[i];
        g_dinv[i] = (d > 0) ? rsqrtf((float)d) : 0.0f;
    }
}

__global__ void scan1_kernel() {
    __shared__ int s[SCAN_B];
    int tid = threadIdx.x;
    int gid = blockIdx.x * SCAN_B + tid;
    int v = (gid < NN) ? g_deg[gid] : 0;
    s[tid] = v;
    __syncthreads();
    #pragma unroll
    for (int off = 1; off < SCAN_B; off <<= 1) {
        int t = (tid >= off) ? s[tid - off] : 0;
        __syncthreads();
        s[tid] += t;
        __syncthreads();
    }
    if (gid < NN) g_ptr[gid] = s[tid] - v;
    if (tid == SCAN_B - 1) g_bsum[blockIdx.x] = s[tid];
}

__global__ void scan2_kernel() {
    __shared__ int s[512];
    int tid = threadIdx.x;
    int v = (tid < NBLK) ? g_bsum[tid] : 0;
    s[tid] = v;
    __syncthreads();
    #pragma unroll
    for (int off = 1; off < 512; off <<= 1) {
        int t = (tid >= off) ? s[tid - off] : 0;
        __syncthreads();
        s[tid] += t;
        __syncthreads();
    }
    if (tid < NBLK) g_boff[tid] = s[tid] - v;
    if (tid == NBLK - 1) g_ptr[NN] = s[tid];
}

__global__ void scan3_kernel() {
    int gid = blockIdx.x * SCAN_B + threadIdx.x;
    if (gid < NN) g_ptr[gid] += g_boff[blockIdx.x];
}

__global__ void fill_kernel(const int* __restrict__ row32,
                            const int* __restrict__ col32) {
    int e = blockIdx.x * blockDim.x + threadIdx.x;
    if (e < EE) {
        int r = row32[e];
        int c = col32[e];
        if (r < 0 || r >= NN) r = 0;
        if (c < 0 || c >= NN) c = 0;
        float nrm = g_dinv[r] * g_dinv[c];
        int pos = g_ptr[c] + atomicAdd(&g_fill[c], 1);
        g_sn[pos] = make_int2(r, __float_as_int(nrm));
        g_tg[pos] = c;
    }
}

// ---------------- elementwise (vectorized, verbatim) ----------------

__global__ void init_kernel(const float* __restrict__ emb, float* __restrict__ out) {
    int i = blockIdx.x * blockDim.x + threadIdx.x;
    if (i < ND4) {
        float4 v = reinterpret_cast<const float4*>(emb)[i];
        reinterpret_cast<float4*>(g_xa)[i] = v;
        reinterpret_cast<float4*>(out)[i] = v;
    }
}

__global__ void zero_x_kernel(int which) {
    int i = blockIdx.x * blockDim.x + threadIdx.x;
    if (i < ND4) {
        float4 z = make_float4(0.f, 0.f, 0.f, 0.f);
        if (which == 0) reinterpret_cast<float4*>(g_xb)[i] = z;
        else            reinterpret_cast<float4*>(g_xa)[i] = z;
    }
}

__global__ void accum_kernel(float* __restrict__ out, int which, float scale) {
    int i = blockIdx.x * blockDim.x + threadIdx.x;
    if (i < ND4) {
        float4 xv = (which == 0) ? reinterpret_cast<const float4*>(g_xb)[i]
                                 : reinterpret_cast<const float4*>(g_xa)[i];
        float4 ov = reinterpret_cast<const float4*>(out)[i];
        ov.x = (ov.x + xv.x) * scale;
        ov.y = (ov.y + xv.y) * scale;
        ov.z = (ov.z + xv.z) * scale;
        ov.w = (ov.w + xv.w) * scale;
        reinterpret_cast<float4*>(out)[i] = ov;
    }
}

// ---------------- permuted oct-merged scatter ----------------
// 16-thread group p processes sorted oct o = (p*PRIME) mod NOCT:
// edges 8o..8o+7 mostly share one target (E[REDs] ~ 1.22) -> typically ONE red.v4.
// Coprime-stride permutation keeps same-target REDs temporally spread.
__device__ __forceinline__ void red4(float4* dst, float4 v) {
    asm volatile("red.global.add.v4.f32 [%0], {%1,%2,%3,%4};"
                 :: "l"(dst), "f"(v.x), "f"(v.y), "f"(v.z), "f"(v.w)
                 : "memory");
}

__device__ __forceinline__ void acc_add(float4& a, const float4& b) {
    a.x += b.x; a.y += b.y; a.z += b.z; a.w += b.w;
}

template <int DIR>
__global__ __launch_bounds__(256) void oscatter_kernel() {
    const float* xin  = DIR == 0 ? g_xa : g_xb;
    float*       xout = DIR == 0 ? g_xb : g_xa;

    int gid = blockIdx.x * 256 + threadIdx.x;   // < 6.4M, fits int
    int c = gid & 15;
    int p = gid >> 4;
    if (p >= NOCT) return;
    int o = (int)(((long long)p * PRIME) % NOCT);

    const int4* sn4 = reinterpret_cast<const int4*>(g_sn);
    const int4* tg4 = reinterpret_cast<const int4*>(g_tg);
    int4 s0 = __ldg(sn4 + 4 * o);
    int4 s1 = __ldg(sn4 + 4 * o + 1);
    int4 s2 = __ldg(sn4 + 4 * o + 2);
    int4 s3 = __ldg(sn4 + 4 * o + 3);
    int4 t0 = __ldg(tg4 + 2 * o);               // targets 0..3
    int4 t1 = __ldg(tg4 + 2 * o + 1);           // targets 4..7

    // issue all 8 gathers up front (max MLP)
    const float4* x4 = reinterpret_cast<const float4*>(xin);
    float4 v0 = __ldg(x4 + (size_t)s0.x * 16 + c);
    float4 v1 = __ldg(x4 + (size_t)s0.z * 16 + c);
    float4 v2 = __ldg(x4 + (size_t)s1.x * 16 + c);
    float4 v3 = __ldg(x4 + (size_t)s1.z * 16 + c);
    float4 v4 = __ldg(x4 + (size_t)s2.x * 16 + c);
    float4 v5 = __ldg(x4 + (size_t)s2.z * 16 + c);
    float4 v6 = __ldg(x4 + (size_t)s3.x * 16 + c);
    float4 v7 = __ldg(x4 + (size_t)s3.z * 16 + c);

    float n0 = __int_as_float(s0.y), n1 = __int_as_float(s0.w);
    float n2 = __int_as_float(s1.y), n3 = __int_as_float(s1.w);
    float n4 = __int_as_float(s2.y), n5 = __int_as_float(s2.w);
    float n6 = __int_as_float(s3.y), n7 = __int_as_float(s3.w);

    float4 m0 = make_float4(n0*v0.x, n0*v0.y, n0*v0.z, n0*v0.w);
    float4 m1 = make_float4(n1*v1.x, n1*v1.y, n1*v1.z, n1*v1.w);
    float4 m2 = make_float4(n2*v2.x, n2*v2.y, n2*v2.z, n2*v2.w);
    float4 m3 = make_float4(n3*v3.x, n3*v3.y, n3*v3.z, n3*v3.w);
    float4 m4 = make_float4(n4*v4.x, n4*v4.y, n4*v4.z, n4*v4.w);
    float4 m5 = make_float4(n5*v5.x, n5*v5.y, n5*v5.z, n5*v5.w);
    float4 m6 = make_float4(n6*v6.x, n6*v6.y, n6*v6.z, n6*v6.w);
    float4 m7 = make_float4(n7*v7.x, n7*v7.y, n7*v7.z, n7*v7.w);

    float4* out4 = reinterpret_cast<float4*>(xout);

    // run-merge chain (group-uniform; sorted so equal targets adjacent)
    float4 acc = m0;
    int cur = t0.x;
    if (t0.y == cur) acc_add(acc, m1);
    else { red4(out4 + (size_t)cur * 16 + c, acc); cur = t0.y; acc = m1; }
    if (t0.z == cur) acc_add(acc, m2);
    else { red4(out4 + (size_t)cur * 16 + c, acc); cur = t0.z; acc = m2; }
    if (t0.w == cur) acc_add(acc, m3);
    else { red4(out4 + (size_t)cur * 16 + c, acc); cur = t0.w; acc = m3; }
    if (t1.x == cur) acc_add(acc, m4);
    else { red4(out4 + (size_t)cur * 16 + c, acc); cur = t1.x; acc = m4; }
    if (t1.y == cur) acc_add(acc, m5);
    else { red4(out4 + (size_t)cur * 16 + c, acc); cur = t1.y; acc = m5; }
    if (t1.z == cur) acc_add(acc, m6);
    else { red4(out4 + (size_t)cur * 16 + c, acc); cur = t1.z; acc = m6; }
    if (t1.w == cur) acc_add(acc, m7);
    else { red4(out4 + (size_t)cur * 16 + c, acc); cur = t1.w; acc = m7; }
    red4(out4 + (size_t)cur * 16 + c, acc);
}

// ---------------- launch ----------------

extern "C" void kernel_launch(void* const* d_in, const int* in_sizes, int n_in,
                              void* d_out, int out_size) {
    const float* emb = (const float*)d_in[0];
    const int* edge = (const int*)d_in[1];   // [2, EE] int32
    const int* row32 = edge;
    const int* col32 = edge + EE;
    float* out = (float*)d_out;

    const int T = 256;
    int gN  = (NN + T - 1) / T;
    int gE  = (EE + T - 1) / T;
    int gV  = (ND4 + T - 1) / T;
    int gS  = (NOCT * 16 + T - 1) / T;      // 25,000 blocks

    // build target-sorted edge list
    zero_counts_kernel<<<gN, T>>>();
    count_deg_kernel<<<gE, T>>>(col32);
    dinv_kernel<<<gN, T>>>();
    scan1_kernel<<<NBLK, SCAN_B>>>();
    scan2_kernel<<<1, 512>>>();
    scan3_kernel<<<NBLK, SCAN_B>>>();
    fill_kernel<<<gE, T>>>(row32, col32);

    init_kernel<<<gV, T>>>(emb, out);

    // layer 0: xa -> xb
    zero_x_kernel<<<gV, T>>>(0);
    oscatter_kernel<0><<<gS, T>>>();
    accum_kernel<<<gV, T>>>(out, 0, 1.0f);

    // layer 1: xb -> xa
    zero_x_kernel<<<gV, T>>>(1);
    oscatter_kernel<1><<<gS, T>>>();
    accum_kernel<<<gV, T>>>(out, 1, 1.0f);

    // layer 2: xa -> xb (fold /4 into final accumulate)
    zero_x_kernel<<<gV, T>>>(0);
    oscatter_kernel<0><<<gS, T>>>();
    accum_kernel<<<gV, T>>>(out, 0, 0.25f);
}